// round 15
// baseline (speedup 1.0000x reference)
#include <cuda_runtime.h>
#include <math.h>
#include <stdint.h>

#define NN    8192
#define DD    512
#define NBAGS 64
#define BAG   128
#define TOPK  16

#define CJOBS  256      // corr jobs: (bag, quarter) 32x128 tiles
#define GRID_A 444      // 148 SMs x 3 CTAs
#define CHUNK4 65536    // float4 zeros per corr job (256/thread)

// ---- scratch (static device globals: no allocation at runtime) ----
static __device__ float    g_corr[NBAGS * BAG * BAG]; // per-bag cosine blocks (4 MB)
static __device__ int      g_deg[NN];                 // per-node in-degree
static __device__ unsigned g_rowmask[NN][4];          // kept-edge bitmask per row
static __device__ float    g_w[NN];                   // per-row GCN weight
static __device__ float    g_y[NBAGS * DD];           // per-bag weighted feature sum
static __device__ int      g_jobctr;                  // dynamic job counter

// ---------------------------------------------------------------------------
// fused_A: 256 work-stolen corr quarter-tiles (32 rows x 128 cols, K=512)
// with the 268 MB output zero-fill interleaved into the k-loop. Zero stores
// use __stcs (evict-first) so the never-re-read zeros don't sweep F/corr out
// of L2. 3 CTAs/SM so extra warps absorb STG issue cost + smem latency.
// Row norms folded in-loop (bit-identical k-ascending fmaf chain).
// ---------------------------------------------------------------------------
__global__ __launch_bounds__(256, 3) void fused_A(const float* __restrict__ F,
                                                  float4* __restrict__ outz,
                                                  int total4) {
    __shared__ float Cs[2][16 * 132];   // k-major 128-row tile, padded
    __shared__ float ninv_s[128];
    __shared__ int   job_s;
    int tid = threadIdx.x;
    int tx = tid & 15, ty = tid >> 4;   // math: 2 rows x 8 cols per thread
    int r = tid & 127, h = tid >> 7;    // staging: row, k-half

    if (blockIdx.x < 32) g_deg[blockIdx.x * 256 + tid] = 0;

    const float4 z4 = make_float4(0.f, 0.f, 0.f, 0.f);

    for (;;) {
        __syncthreads();                 // protect smem reuse across jobs
        if (tid == 0) job_s = atomicAdd(&g_jobctr, 1);
        __syncthreads();
        int job = job_s;
        if (job >= CJOBS) break;

        int g = job >> 2, q = job & 3;   // bag, row-quarter
        const float* fb = F + (size_t)g * BAG * DD;

        float acc[2][8];
#pragma unroll
        for (int i = 0; i < 2; i++)
#pragma unroll
            for (int j = 0; j < 8; j++) acc[i][j] = 0.f;
        float ss = 0.f;                  // row-norm accumulator (tid<128)

        size_t zbase = (size_t)job * CHUNK4 + tid;

        // prefetch k-tile 0 (whole bag's 128 rows, 16 k's)
        float4 rb0 = *(const float4*)(fb + (size_t)r * DD + h * 8);
        float4 rb1 = *(const float4*)(fb + (size_t)r * DD + h * 8 + 4);

        int buf = 0;
        for (int k0 = 0; k0 < DD; k0 += 16) {
            float* cs = Cs[buf];
            cs[(h * 8 + 0) * 132 + r] = rb0.x;
            cs[(h * 8 + 1) * 132 + r] = rb0.y;
            cs[(h * 8 + 2) * 132 + r] = rb0.z;
            cs[(h * 8 + 3) * 132 + r] = rb0.w;
            cs[(h * 8 + 4) * 132 + r] = rb1.x;
            cs[(h * 8 + 5) * 132 + r] = rb1.y;
            cs[(h * 8 + 6) * 132 + r] = rb1.z;
            cs[(h * 8 + 7) * 132 + r] = rb1.w;
            __syncthreads();

            if (k0 + 16 < DD) {          // prefetch next k-tile under compute
                rb0 = *(const float4*)(fb + (size_t)r * DD + k0 + 16 + h * 8);
                rb1 = *(const float4*)(fb + (size_t)r * DD + k0 + 16 + h * 8 + 4);
            }

            // interleaved zero-fill: 8 streaming STG.128 per thread
            {
                size_t p = zbase + (size_t)(k0 >> 4) * 8 * 256;
#pragma unroll
                for (int s = 0; s < 8; s++)
                    __stcs(&outz[p + (size_t)s * 256], z4);
            }

            // row-norm partial: k-ascending chain, bit-identical to norms_kernel
            if (tid < 128) {
#pragma unroll
                for (int k = 0; k < 16; k++) {
                    float x = cs[k * 132 + tid];
                    ss = fmaf(x, x, ss);
                }
            }

#pragma unroll
            for (int k = 0; k < 16; k++) {
                float a0 = cs[k * 132 + q * 32 + ty * 2];
                float a1 = cs[k * 132 + q * 32 + ty * 2 + 1];
                float4 b0 = *(const float4*)&cs[k * 132 + tx * 8];
                float4 b1 = *(const float4*)&cs[k * 132 + tx * 8 + 4];
                float b[8] = {b0.x, b0.y, b0.z, b0.w, b1.x, b1.y, b1.z, b1.w};
#pragma unroll
                for (int j = 0; j < 8; j++) {
                    acc[0][j] = fmaf(a0, b[j], acc[0][j]);
                    acc[1][j] = fmaf(a1, b[j], acc[1][j]);
                }
            }
            buf ^= 1;
        }

        if (tid < 128) ninv_s[tid] = 1.0f / sqrtf(ss);
        __syncthreads();

        // epilogue: normalize and store this quarter's rows
        float nj[8];
#pragma unroll
        for (int j = 0; j < 8; j++) nj[j] = ninv_s[tx * 8 + j];
        float* cg = g_corr + ((size_t)g * BAG + q * 32) * BAG;
#pragma unroll
        for (int i = 0; i < 2; i++) {
            int rr = ty * 2 + i;
            float ni = ninv_s[q * 32 + rr];
            float4 v0 = make_float4(acc[i][0] * ni * nj[0], acc[i][1] * ni * nj[1],
                                    acc[i][2] * ni * nj[2], acc[i][3] * ni * nj[3]);
            float4 v1 = make_float4(acc[i][4] * ni * nj[4], acc[i][5] * ni * nj[5],
                                    acc[i][6] * ni * nj[6], acc[i][7] * ni * nj[7]);
            *(float4*)&cg[(size_t)rr * BAG + tx * 8]     = v0;
            *(float4*)&cg[(size_t)rr * BAG + tx * 8 + 4] = v1;
        }
    }

    // tail of the zero-fill not covered by job chunks
    for (size_t i = (size_t)CJOBS * CHUNK4 + (size_t)blockIdx.x * 256 + tid;
         i < (size_t)total4; i += (size_t)GRID_A * 256)
        __stcs(&outz[i], z4);
}

// ---------------------------------------------------------------------------
// B1: top-16. 256 blocks (bag x quarter, 8 warps x 4 rows). Proven shfl
// argmax (lowest-index ties). Degrees -> global atomics.
// ---------------------------------------------------------------------------
__global__ __launch_bounds__(256) void topk_kernel(float* __restrict__ adj) {
    int g = blockIdx.x, q = blockIdx.y;
    int tid = threadIdx.x, warp = tid >> 5, lane = tid & 31;

    for (int rr = 0; rr < 4; rr++) {
        int i = q * 32 + warp * 4 + rr;
        const float* row = g_corr + ((size_t)g * BAG + i) * BAG;
        float v0 = row[lane], v1 = row[lane + 32], v2 = row[lane + 64], v3 = row[lane + 96];
        unsigned rm0 = 0, rm1 = 0, rm2 = 0, rm3 = 0;

        for (int t = 0; t < TOPK; t++) {
            float bv = v0; int bidx = lane;
            if (v1 > bv) { bv = v1; bidx = lane + 32; }
            if (v2 > bv) { bv = v2; bidx = lane + 64; }
            if (v3 > bv) { bv = v3; bidx = lane + 96; }
#pragma unroll
            for (int o = 16; o > 0; o >>= 1) {
                float ov = __shfl_xor_sync(0xffffffffu, bv, o);
                int   oi = __shfl_xor_sync(0xffffffffu, bidx, o);
                if (ov > bv || (ov == bv && oi < bidx)) { bv = ov; bidx = oi; }
            }
            if (bv <= 0.0f) break;  // remaining in-bag values lose to out-of-bag zeros
            if ((bidx & 31) == lane) {   // clear the winner
                int qq = bidx >> 5;
                if (qq == 0) v0 = -3e38f; else if (qq == 1) v1 = -3e38f;
                else if (qq == 2) v2 = -3e38f; else v3 = -3e38f;
            }
            int qq = bidx >> 5; unsigned bit = 1u << (bidx & 31);
            rm0 |= (qq == 0) ? bit : 0u; rm1 |= (qq == 1) ? bit : 0u;
            rm2 |= (qq == 2) ? bit : 0u; rm3 |= (qq == 3) ? bit : 0u;
            if (lane == 0) {
                adj[((size_t)(g * BAG + i)) * NN + g * BAG + bidx] = bv;
                atomicAdd(&g_deg[g * BAG + bidx], 1);
            }
        }
        if (lane == 0) {
            g_rowmask[g * BAG + i][0] = rm0; g_rowmask[g * BAG + i][1] = rm1;
            g_rowmask[g * BAG + i][2] = rm2; g_rowmask[g * BAG + i][3] = rm3;
        }
    }
}

// ---------------------------------------------------------------------------
// B2: w_i = dis_i * sum_{j in rowmask(i)} dis_j   (64 blocks x 128)
// ---------------------------------------------------------------------------
__global__ __launch_bounds__(128) void w_kernel() {
    __shared__ float dis_s[128];
    int g = blockIdx.x, tid = threadIdx.x;
    dis_s[tid] = 1.0f / sqrtf((float)g_deg[g * BAG + tid]);
    __syncthreads();
    float s = 0.f;
#pragma unroll
    for (int q = 0; q < 4; q++) {
        unsigned m = g_rowmask[g * BAG + tid][q];
        while (m) { int j = __ffs(m) - 1; s += dis_s[q * 32 + j]; m &= m - 1; }
    }
    g_w[g * BAG + tid] = dis_s[tid] * s;
}

// ---------------------------------------------------------------------------
// B3: y[g,d] = sum_i w_i * F[g*128+i, d].
// grid (64,4) x 256: 128 cols x 2 row-halves per block, smem combine.
// ---------------------------------------------------------------------------
__global__ __launch_bounds__(256) void y_kernel(const float* __restrict__ F) {
    __shared__ float w_s[128];
    __shared__ float part[128];
    int g = blockIdx.x, c = blockIdx.y, tid = threadIdx.x;
    if (tid < 128) w_s[tid] = g_w[g * BAG + tid];
    __syncthreads();
    int col = c * 128 + (tid & 127);
    int half = tid >> 7;
    const float* fb = F + ((size_t)g * BAG + half * 64) * DD + col;
    float a0 = 0.f, a1 = 0.f, a2 = 0.f, a3 = 0.f;
#pragma unroll 4
    for (int i = 0; i < 64; i += 4) {
        a0 = fmaf(w_s[half * 64 + i],     fb[(size_t)i * DD],       a0);
        a1 = fmaf(w_s[half * 64 + i + 1], fb[(size_t)(i + 1) * DD], a1);
        a2 = fmaf(w_s[half * 64 + i + 2], fb[(size_t)(i + 2) * DD], a2);
        a3 = fmaf(w_s[half * 64 + i + 3], fb[(size_t)(i + 3) * DD], a3);
    }
    float a = (a0 + a1) + (a2 + a3);
    if (half) part[tid & 127] = a;
    __syncthreads();
    if (!half) g_y[g * DD + col] = a + part[tid & 127];
}

// ---------------------------------------------------------------------------
// B4: agg[g,n] = sum_k y[g,k] * W[k,n] + 128*b[n].
// grid (64,4) x 256: 128 cols x 2 k-halves, 8 chains each, smem combine.
// ---------------------------------------------------------------------------
__global__ __launch_bounds__(256) void agg_kernel(const float* __restrict__ W,
                                                  const float* __restrict__ bias,
                                                  float* __restrict__ agg) {
    __shared__ float y_s[DD];
    __shared__ float part[128];
    int g = blockIdx.x, c = blockIdx.y, tid = threadIdx.x;
    y_s[tid] = g_y[g * DD + tid];
    y_s[tid + 256] = g_y[g * DD + tid + 256];
    __syncthreads();
    int col = c * 128 + (tid & 127);
    int half = tid >> 7;
    const float* wp = W + (size_t)half * 256 * DD + col;
    const float* yp = y_s + half * 256;
    float s0 = 0.f, s1 = 0.f, s2 = 0.f, s3 = 0.f;
    float s4 = 0.f, s5 = 0.f, s6 = 0.f, s7 = 0.f;
#pragma unroll 4
    for (int k = 0; k < 256; k += 8) {
        s0 = fmaf(yp[k],     wp[(size_t)k * DD],       s0);
        s1 = fmaf(yp[k + 1], wp[(size_t)(k + 1) * DD], s1);
        s2 = fmaf(yp[k + 2], wp[(size_t)(k + 2) * DD], s2);
        s3 = fmaf(yp[k + 3], wp[(size_t)(k + 3) * DD], s3);
        s4 = fmaf(yp[k + 4], wp[(size_t)(k + 4) * DD], s4);
        s5 = fmaf(yp[k + 5], wp[(size_t)(k + 5) * DD], s5);
        s6 = fmaf(yp[k + 6], wp[(size_t)(k + 6) * DD], s6);
        s7 = fmaf(yp[k + 7], wp[(size_t)(k + 7) * DD], s7);
    }
    float s = ((s0 + s1) + (s2 + s3)) + ((s4 + s5) + (s6 + s7));
    if (half) part[tid & 127] = s;
    __syncthreads();
    if (!half) agg[g * DD + col] = s + part[tid & 127] + 128.0f * bias[col];
}

// ---------------------------------------------------------------------------
extern "C" void kernel_launch(void* const* d_in, const int* in_sizes, int n_in,
                              void* d_out, int out_size) {
    (void)in_sizes; (void)n_in;
    const float* features = (const float*)d_in[0];
    const float* W        = (const float*)d_in[1];
    const float* b        = (const float*)d_in[2];

    float* out = (float*)d_out;
    float* agg = out;                                        // [64, 512]
    float* adj = out + ((size_t)out_size - (size_t)NN * NN); // [8192, 8192]

    void* ctrp = nullptr;
    cudaGetSymbolAddress(&ctrp, g_jobctr);
    cudaMemsetAsync(ctrp, 0, sizeof(int), 0);                // reset job counter

    fused_A<<<GRID_A, 256>>>(features, (float4*)d_out, out_size / 4);
    topk_kernel<<<dim3(NBAGS, 4), 256>>>(adj);
    w_kernel<<<NBAGS, 128>>>();
    y_kernel<<<dim3(NBAGS, 4), 256>>>(features);
    agg_kernel<<<dim3(NBAGS, 4), 256>>>(W, b, agg);
}

// round 16
// speedup vs baseline: 1.2653x; 1.2653x over previous
#include <cuda_runtime.h>
#include <math.h>
#include <stdint.h>

#define NN    8192
#define DD    512
#define NBAGS 64
#define BAG   128
#define TOPK  16

#define CJOBS  256      // corr jobs: (bag, quarter) 32x128 tiles
#define GRID_A 296      // 148 SMs x 2 CTAs
#define CHUNK4 65536    // float4 zeros per corr job (256/thread)

// ---- scratch (static device globals: no allocation at runtime) ----
static __device__ float    g_corr[NBAGS * BAG * BAG]; // per-bag cosine blocks (4 MB)
static __device__ int      g_deg[NN];                 // per-node in-degree
static __device__ unsigned g_rowmask[NN][4];          // kept-edge bitmask per row
static __device__ float    g_w[NN];                   // per-row GCN weight
static __device__ float    g_y[NBAGS * DD];           // per-bag weighted feature sum
static __device__ int      g_jobctr;                  // dynamic job counter

// ---------------------------------------------------------------------------
// fused_A (R14-proven, reverted): 256 work-stolen corr quarter-tiles
// (32 rows x 128 cols, K=512) with the 268 MB output zero-fill interleaved
// into the k-loop (8 fire-and-forget STG.128 per thread per k-tile drain
// under the FMA-bound compute). 2 CTAs/SM — 3 capped regs at ~85 and spilled.
// Row norms folded in-loop (bit-identical k-ascending fmaf chain).
// ---------------------------------------------------------------------------
__global__ __launch_bounds__(256, 2) void fused_A(const float* __restrict__ F,
                                                  float4* __restrict__ outz,
                                                  int total4) {
    __shared__ float Cs[2][16 * 132];   // k-major 128-row tile, padded
    __shared__ float ninv_s[128];
    __shared__ int   job_s;
    int tid = threadIdx.x;
    int tx = tid & 15, ty = tid >> 4;   // math: 2 rows x 8 cols per thread
    int r = tid & 127, h = tid >> 7;    // staging: row, k-half

    if (blockIdx.x < 32) g_deg[blockIdx.x * 256 + tid] = 0;

    const float4 z4 = make_float4(0.f, 0.f, 0.f, 0.f);

    for (;;) {
        __syncthreads();                 // protect smem reuse across jobs
        if (tid == 0) job_s = atomicAdd(&g_jobctr, 1);
        __syncthreads();
        int job = job_s;
        if (job >= CJOBS) break;

        int g = job >> 2, q = job & 3;   // bag, row-quarter
        const float* fb = F + (size_t)g * BAG * DD;

        float acc[2][8];
#pragma unroll
        for (int i = 0; i < 2; i++)
#pragma unroll
            for (int j = 0; j < 8; j++) acc[i][j] = 0.f;
        float ss = 0.f;                  // row-norm accumulator (tid<128)

        size_t zbase = (size_t)job * CHUNK4 + tid;

        // prefetch k-tile 0 (whole bag's 128 rows, 16 k's)
        float4 rb0 = *(const float4*)(fb + (size_t)r * DD + h * 8);
        float4 rb1 = *(const float4*)(fb + (size_t)r * DD + h * 8 + 4);

        int buf = 0;
        for (int k0 = 0; k0 < DD; k0 += 16) {
            float* cs = Cs[buf];
            cs[(h * 8 + 0) * 132 + r] = rb0.x;
            cs[(h * 8 + 1) * 132 + r] = rb0.y;
            cs[(h * 8 + 2) * 132 + r] = rb0.z;
            cs[(h * 8 + 3) * 132 + r] = rb0.w;
            cs[(h * 8 + 4) * 132 + r] = rb1.x;
            cs[(h * 8 + 5) * 132 + r] = rb1.y;
            cs[(h * 8 + 6) * 132 + r] = rb1.z;
            cs[(h * 8 + 7) * 132 + r] = rb1.w;
            __syncthreads();

            if (k0 + 16 < DD) {          // prefetch next k-tile under compute
                rb0 = *(const float4*)(fb + (size_t)r * DD + k0 + 16 + h * 8);
                rb1 = *(const float4*)(fb + (size_t)r * DD + k0 + 16 + h * 8 + 4);
            }

            // interleaved zero-fill: 8 fire-and-forget STG.128 per thread
            {
                size_t p = zbase + (size_t)(k0 >> 4) * 8 * 256;
#pragma unroll
                for (int s = 0; s < 8; s++) outz[p + (size_t)s * 256] = z4;
            }

            // row-norm partial: k-ascending chain, bit-identical to norms_kernel
            if (tid < 128) {
#pragma unroll
                for (int k = 0; k < 16; k++) {
                    float x = cs[k * 132 + tid];
                    ss = fmaf(x, x, ss);
                }
            }

#pragma unroll
            for (int k = 0; k < 16; k++) {
                float a0 = cs[k * 132 + q * 32 + ty * 2];
                float a1 = cs[k * 132 + q * 32 + ty * 2 + 1];
                float4 b0 = *(const float4*)&cs[k * 132 + tx * 8];
                float4 b1 = *(const float4*)&cs[k * 132 + tx * 8 + 4];
                float b[8] = {b0.x, b0.y, b0.z, b0.w, b1.x, b1.y, b1.z, b1.w};
#pragma unroll
                for (int j = 0; j < 8; j++) {
                    acc[0][j] = fmaf(a0, b[j], acc[0][j]);
                    acc[1][j] = fmaf(a1, b[j], acc[1][j]);
                }
            }
            buf ^= 1;
        }

        if (tid < 128) ninv_s[tid] = 1.0f / sqrtf(ss);
        __syncthreads();

        // epilogue: normalize and store this quarter's rows
        float nj[8];
#pragma unroll
        for (int j = 0; j < 8; j++) nj[j] = ninv_s[tx * 8 + j];
        float* cg = g_corr + ((size_t)g * BAG + q * 32) * BAG;
#pragma unroll
        for (int i = 0; i < 2; i++) {
            int rr = ty * 2 + i;
            float ni = ninv_s[q * 32 + rr];
            float4 v0 = make_float4(acc[i][0] * ni * nj[0], acc[i][1] * ni * nj[1],
                                    acc[i][2] * ni * nj[2], acc[i][3] * ni * nj[3]);
            float4 v1 = make_float4(acc[i][4] * ni * nj[4], acc[i][5] * ni * nj[5],
                                    acc[i][6] * ni * nj[6], acc[i][7] * ni * nj[7]);
            *(float4*)&cg[(size_t)rr * BAG + tx * 8]     = v0;
            *(float4*)&cg[(size_t)rr * BAG + tx * 8 + 4] = v1;
        }
    }

    // tail of the zero-fill not covered by job chunks
    for (size_t i = (size_t)CJOBS * CHUNK4 + (size_t)blockIdx.x * 256 + tid;
         i < (size_t)total4; i += (size_t)GRID_A * 256)
        outz[i] = z4;
}

// ---------------------------------------------------------------------------
// B1: top-16, ONE ROW PER WARP (was 4 serial rows/warp). grid (64,4) x 1024:
// 8192 warps, each runs the proven 16-step shfl argmax (lowest-index ties)
// on its own row. 4x less serial latency per warp.
// ---------------------------------------------------------------------------
__global__ __launch_bounds__(1024) void topk_kernel(float* __restrict__ adj) {
    int g = blockIdx.x, q = blockIdx.y;
    int tid = threadIdx.x, warp = tid >> 5, lane = tid & 31;

    int i = q * 32 + warp;               // row within bag
    const float* row = g_corr + ((size_t)g * BAG + i) * BAG;
    float v0 = row[lane], v1 = row[lane + 32], v2 = row[lane + 64], v3 = row[lane + 96];
    unsigned rm0 = 0, rm1 = 0, rm2 = 0, rm3 = 0;

    for (int t = 0; t < TOPK; t++) {
        float bv = v0; int bidx = lane;
        if (v1 > bv) { bv = v1; bidx = lane + 32; }
        if (v2 > bv) { bv = v2; bidx = lane + 64; }
        if (v3 > bv) { bv = v3; bidx = lane + 96; }
#pragma unroll
        for (int o = 16; o > 0; o >>= 1) {
            float ov = __shfl_xor_sync(0xffffffffu, bv, o);
            int   oi = __shfl_xor_sync(0xffffffffu, bidx, o);
            if (ov > bv || (ov == bv && oi < bidx)) { bv = ov; bidx = oi; }
        }
        if (bv <= 0.0f) break;  // remaining in-bag values lose to out-of-bag zeros
        if ((bidx & 31) == lane) {   // clear the winner
            int qq = bidx >> 5;
            if (qq == 0) v0 = -3e38f; else if (qq == 1) v1 = -3e38f;
            else if (qq == 2) v2 = -3e38f; else v3 = -3e38f;
        }
        int qq = bidx >> 5; unsigned bit = 1u << (bidx & 31);
        rm0 |= (qq == 0) ? bit : 0u; rm1 |= (qq == 1) ? bit : 0u;
        rm2 |= (qq == 2) ? bit : 0u; rm3 |= (qq == 3) ? bit : 0u;
        if (lane == 0) {
            adj[((size_t)(g * BAG + i)) * NN + g * BAG + bidx] = bv;
            atomicAdd(&g_deg[g * BAG + bidx], 1);
        }
    }
    if (lane == 0) {
        g_rowmask[g * BAG + i][0] = rm0; g_rowmask[g * BAG + i][1] = rm1;
        g_rowmask[g * BAG + i][2] = rm2; g_rowmask[g * BAG + i][3] = rm3;
    }
}

// ---------------------------------------------------------------------------
// B2: w_i = dis_i * sum_{j in rowmask(i)} dis_j   (64 blocks x 128)
// ---------------------------------------------------------------------------
__global__ __launch_bounds__(128) void w_kernel() {
    __shared__ float dis_s[128];
    int g = blockIdx.x, tid = threadIdx.x;
    dis_s[tid] = 1.0f / sqrtf((float)g_deg[g * BAG + tid]);
    __syncthreads();
    float s = 0.f;
#pragma unroll
    for (int q = 0; q < 4; q++) {
        unsigned m = g_rowmask[g * BAG + tid][q];
        while (m) { int j = __ffs(m) - 1; s += dis_s[q * 32 + j]; m &= m - 1; }
    }
    g_w[g * BAG + tid] = dis_s[tid] * s;
}

// ---------------------------------------------------------------------------
// B3: y[g,d] = sum_i w_i * F[g*128+i, d].
// grid (64,4) x 256: 128 cols x 2 row-halves per block, smem combine.
// ---------------------------------------------------------------------------
__global__ __launch_bounds__(256) void y_kernel(const float* __restrict__ F) {
    __shared__ float w_s[128];
    __shared__ float part[128];
    int g = blockIdx.x, c = blockIdx.y, tid = threadIdx.x;
    if (tid < 128) w_s[tid] = g_w[g * BAG + tid];
    __syncthreads();
    int col = c * 128 + (tid & 127);
    int half = tid >> 7;
    const float* fb = F + ((size_t)g * BAG + half * 64) * DD + col;
    float a0 = 0.f, a1 = 0.f, a2 = 0.f, a3 = 0.f;
#pragma unroll 4
    for (int i = 0; i < 64; i += 4) {
        a0 = fmaf(w_s[half * 64 + i],     fb[(size_t)i * DD],       a0);
        a1 = fmaf(w_s[half * 64 + i + 1], fb[(size_t)(i + 1) * DD], a1);
        a2 = fmaf(w_s[half * 64 + i + 2], fb[(size_t)(i + 2) * DD], a2);
        a3 = fmaf(w_s[half * 64 + i + 3], fb[(size_t)(i + 3) * DD], a3);
    }
    float a = (a0 + a1) + (a2 + a3);
    if (half) part[tid & 127] = a;
    __syncthreads();
    if (!half) g_y[g * DD + col] = a + part[tid & 127];
}

// ---------------------------------------------------------------------------
// B4: agg[g,n] = sum_k y[g,k] * W[k,n] + 128*b[n].
// grid (64,4) x 256: 128 cols x 2 k-halves, 8 chains each, smem combine.
// ---------------------------------------------------------------------------
__global__ __launch_bounds__(256) void agg_kernel(const float* __restrict__ W,
                                                  const float* __restrict__ bias,
                                                  float* __restrict__ agg) {
    __shared__ float y_s[DD];
    __shared__ float part[128];
    int g = blockIdx.x, c = blockIdx.y, tid = threadIdx.x;
    y_s[tid] = g_y[g * DD + tid];
    y_s[tid + 256] = g_y[g * DD + tid + 256];
    __syncthreads();
    int col = c * 128 + (tid & 127);
    int half = tid >> 7;
    const float* wp = W + (size_t)half * 256 * DD + col;
    const float* yp = y_s + half * 256;
    float s0 = 0.f, s1 = 0.f, s2 = 0.f, s3 = 0.f;
    float s4 = 0.f, s5 = 0.f, s6 = 0.f, s7 = 0.f;
#pragma unroll 4
    for (int k = 0; k < 256; k += 8) {
        s0 = fmaf(yp[k],     wp[(size_t)k * DD],       s0);
        s1 = fmaf(yp[k + 1], wp[(size_t)(k + 1) * DD], s1);
        s2 = fmaf(yp[k + 2], wp[(size_t)(k + 2) * DD], s2);
        s3 = fmaf(yp[k + 3], wp[(size_t)(k + 3) * DD], s3);
        s4 = fmaf(yp[k + 4], wp[(size_t)(k + 4) * DD], s4);
        s5 = fmaf(yp[k + 5], wp[(size_t)(k + 5) * DD], s5);
        s6 = fmaf(yp[k + 6], wp[(size_t)(k + 6) * DD], s6);
        s7 = fmaf(yp[k + 7], wp[(size_t)(k + 7) * DD], s7);
    }
    float s = ((s0 + s1) + (s2 + s3)) + ((s4 + s5) + (s6 + s7));
    if (half) part[tid & 127] = s;
    __syncthreads();
    if (!half) agg[g * DD + col] = s + part[tid & 127] + 128.0f * bias[col];
}

// ---------------------------------------------------------------------------
extern "C" void kernel_launch(void* const* d_in, const int* in_sizes, int n_in,
                              void* d_out, int out_size) {
    (void)in_sizes; (void)n_in;
    const float* features = (const float*)d_in[0];
    const float* W        = (const float*)d_in[1];
    const float* b        = (const float*)d_in[2];

    float* out = (float*)d_out;
    float* agg = out;                                        // [64, 512]
    float* adj = out + ((size_t)out_size - (size_t)NN * NN); // [8192, 8192]

    void* ctrp = nullptr;
    cudaGetSymbolAddress(&ctrp, g_jobctr);
    cudaMemsetAsync(ctrp, 0, sizeof(int), 0);                // reset job counter

    fused_A<<<GRID_A, 256>>>(features, (float4*)d_out, out_size / 4);
    topk_kernel<<<dim3(NBAGS, 4), 1024>>>(adj);
    w_kernel<<<NBAGS, 128>>>();
    y_kernel<<<dim3(NBAGS, 4), 256>>>(features);
    agg_kernel<<<dim3(NBAGS, 4), 256>>>(W, b, agg);
}